// round 3
// baseline (speedup 1.0000x reference)
#include <cuda_runtime.h>
#include <cstdint>

#define BATCHN 16384
#define NUMA   512
#define CONSN  512

#define RPW     27                 // rows (slots) per warp; lanes 27..31 duplicate slots 0..4
#define NWARPS  4
#define STRIDE  515                // floats per row slot; word[512]=1.0f (pos neutral), word[513]=0.0f (neg neutral)
#define ROWF    (RPW*STRIDE)       // floats per warp region
#define ECAP    96                 // max entries per list (pos / neg); Binom(512,1/12) mean 42.7, sd 6.3 -> safe
#define ESTRIDE 192                // entries per constraint: pos at [0..96), neg at [96..192)
#define GRIDN   152                // GB300: 152 SMs, one 222KB block each -> single wave
#define SMEM_BYTES (NWARPS*ROWF*4 + 2*ESTRIDE*4)

__device__ unsigned int g_ent[CONSN * ESTRIDE];   // byte offsets (atom*4), padded with neutral offsets
__device__ int4         g_meta[CONSN];            // {np4 chunks, nn4 chunks, head byte-offset, sign}

// ---------------------------------------------------------------------------
// Prep: compact the dense 512x512 masks into per-constraint sparse offset
// lists (order inside a list is irrelevant: min/max are exact & commutative).
// head_sign dtype is decoded defensively: the reference emits jnp.bool_, but
// the harness widens to a supported dtype (int32 most likely). We scan the
// first 512 bytes (safe under every candidate encoding): a genuine uint8
// buffer has nonzero bytes at offsets %4!=0 (w.p. 1 - 2^-384); otherwise the
// encoding is 4-byte and (dword != 0) is correct for both int32 0/1 and
// float32 0.0/1.0.
// ---------------------------------------------------------------------------
__global__ void prep_kernel(const float* __restrict__ pos_body,
                            const float* __restrict__ neg_body,
                            const int* __restrict__ head_atom,
                            const unsigned char* __restrict__ head_sign) {
    int c = blockIdx.x;
    __shared__ int cnt[2];
    __shared__ int is_u8;
    if (threadIdx.x == 0) { cnt[0] = 0; cnt[1] = 0; is_u8 = 0; }
    __syncthreads();
    // dtype sniff: bytes at offset %4 != 0 within the first 512 bytes
    for (int t = threadIdx.x; t < CONSN; t += blockDim.x) {
        if ((t & 3) && head_sign[t]) atomicOr(&is_u8, 1);
    }
    const float* pr = pos_body + c * NUMA;
    const float* nr = neg_body + c * NUMA;
    for (int j = threadIdx.x; j < NUMA; j += blockDim.x) {
        if (pr[j] > 0.5f) {
            int k = atomicAdd(&cnt[0], 1);
            if (k < ECAP) g_ent[c * ESTRIDE + k] = (unsigned)(j * 4);
        }
        if (nr[j] > 0.5f) {
            int k = atomicAdd(&cnt[1], 1);
            if (k < ECAP) g_ent[c * ESTRIDE + ECAP + k] = (unsigned)(j * 4);
        }
    }
    __syncthreads();
    if (threadIdx.x == 0) {
        int np = min(cnt[0], ECAP), nn = min(cnt[1], ECAP);
        int np4 = (np + 3) >> 2; if (np4 < 2) np4 = 2;   // pipeline needs >= 2 chunks
        int nn4 = (nn + 3) >> 2; if (nn4 < 2) nn4 = 2;
        for (int k = np; k < np4 * 4; k++) g_ent[c * ESTRIDE + k]        = 512u * 4u; // -> 1.0f (min-neutral)
        for (int k = nn; k < nn4 * 4; k++) g_ent[c * ESTRIDE + ECAP + k] = 513u * 4u; // -> 0.0f (max-neutral)
        int sign;
        if (is_u8) {
            sign = (head_sign[c] != 0);
        } else {
            sign = (((const unsigned int*)head_sign)[c] != 0u);  // int32 0/1 or float32 0.0/1.0
        }
        g_meta[c] = make_int4(np4, nn4, head_atom[c] * 4, sign);
    }
}

// ---------------------------------------------------------------------------
// Solver: thread-per-row, rows resident in SMEM, 512 sequential constraints.
// All warps in a block run identical control flow (same constraint stream),
// so the per-constraint __syncthreads (for entry staging) is near-free.
// ---------------------------------------------------------------------------
__global__ void __launch_bounds__(128, 1)
solve_kernel(const float* __restrict__ preds, float* __restrict__ out) {
    extern __shared__ float smem[];
    unsigned int* sbuf = (unsigned int*)(smem + NWARPS * ROWF);  // 2 x ESTRIDE staged entries

    const int tid  = threadIdx.x;
    const int warp = tid >> 5;
    const int lane = tid & 31;
    int slot = (lane >= RPW) ? (lane - RPW) : lane;   // duplicate lanes share a slot (benign)

    float* wbase = smem + warp * ROWF;
    char*  lb    = (char*)(wbase + slot * STRIDE);

    const int rowblk = blockIdx.x * (NWARPS * RPW) + warp * RPW;

    // ---- load rows (coalesced, conflict-free stores) ----
    for (int i = 0; i < RPW; i++) {
        int r = rowblk + i; if (r >= BATCHN) r = BATCHN - 1;
        const float* src = preds + (size_t)r * NUMA;
        float* dst = wbase + i * STRIDE;
        #pragma unroll
        for (int k = 0; k < 16; k++) {
            int idx = lane + 32 * k;
            dst[idx] = src[idx];
        }
    }
    if (lane < RPW) { ((float*)lb)[512] = 1.0f; ((float*)lb)[513] = 0.0f; }

    // ---- stage constraint 0 entries ----
    sbuf[tid] = g_ent[tid];
    if (tid < ESTRIDE - 128) sbuf[128 + tid] = g_ent[128 + tid];
    int4 mcur = g_meta[0];
    __syncthreads();

    // register-prefetch constraint 1 (commit after compute; LDG latency overlaps)
    unsigned int s0, s1 = 0; int4 mnext;
    {
        const unsigned int* gn = g_ent + ESTRIDE;
        s0 = gn[tid];
        if (tid < ESTRIDE - 128) s1 = gn[128 + tid];
        mnext = g_meta[1];
    }

    for (int c = 0; c < CONSN; c++) {
        const uint4* pe = (const uint4*)(sbuf + (c & 1) * ESTRIDE);
        const uint4* ne = pe + (ECAP / 4);
        const int np4 = mcur.x, nn4 = mcur.y;

        // ---- pos body: running min of p over pos atoms (== max of 1-p, exactly) ----
        float a0 = 1.0f, a1 = 1.0f, a2 = 1.0f, a3 = 1.0f;
        {
            uint4 e0 = pe[0];
            float p0 = *(const float*)(lb + e0.x), p1 = *(const float*)(lb + e0.y);
            float p2 = *(const float*)(lb + e0.z), p3 = *(const float*)(lb + e0.w);
            uint4 e1 = pe[1];
            #pragma unroll 2
            for (int k = 1; k < np4; k++) {
                uint4 e2 = pe[min(k + 1, np4 - 1)];
                float q0 = *(const float*)(lb + e1.x), q1 = *(const float*)(lb + e1.y);
                float q2 = *(const float*)(lb + e1.z), q3 = *(const float*)(lb + e1.w);
                a0 = fminf(a0, p0); a1 = fminf(a1, p1);
                a2 = fminf(a2, p2); a3 = fminf(a3, p3);
                p0 = q0; p1 = q1; p2 = q2; p3 = q3;
                e1 = e2;
            }
            a0 = fminf(a0, p0); a1 = fminf(a1, p1);
            a2 = fminf(a2, p2); a3 = fminf(a3, p3);
        }

        // ---- neg body: running max of p over neg atoms ----
        float b0 = 0.0f, b1 = 0.0f, b2 = 0.0f, b3 = 0.0f;
        {
            uint4 e0 = ne[0];
            float p0 = *(const float*)(lb + e0.x), p1 = *(const float*)(lb + e0.y);
            float p2 = *(const float*)(lb + e0.z), p3 = *(const float*)(lb + e0.w);
            uint4 e1 = ne[1];
            #pragma unroll 2
            for (int k = 1; k < nn4; k++) {
                uint4 e2 = ne[min(k + 1, nn4 - 1)];
                float q0 = *(const float*)(lb + e1.x), q1 = *(const float*)(lb + e1.y);
                float q2 = *(const float*)(lb + e1.z), q3 = *(const float*)(lb + e1.w);
                b0 = fmaxf(b0, p0); b1 = fmaxf(b1, p1);
                b2 = fmaxf(b2, p2); b3 = fmaxf(b3, p3);
                p0 = q0; p1 = q1; p2 = q2; p3 = q3;
                e1 = e2;
            }
            b0 = fmaxf(b0, p0); b1 = fmaxf(b1, p1);
            b2 = fmaxf(b2, p2); b3 = fmaxf(b3, p3);
        }

        float mnp = fminf(fminf(a0, a1), fminf(a2, a3));
        float mxn = fmaxf(fmaxf(b0, b1), fmaxf(b2, b3));
        float m    = fmaxf(1.0f - mnp, mxn);    // >= 0 by construction (neutrals fold zeros column)
        float cand = 1.0f - m;

        float prev = *(const float*)(lb + mcur.z);
        float upd  = mcur.w ? fmaxf(prev, cand) : fminf(prev, 1.0f - cand);
        *(float*)(lb + mcur.z) = upd;

        // ---- commit staged entries for c+1, then prefetch c+2 ----
        if (c + 1 < CONSN) {
            unsigned int* db = sbuf + ((c + 1) & 1) * ESTRIDE;
            db[tid] = s0;
            if (tid < ESTRIDE - 128) db[128 + tid] = s1;
        }
        __syncthreads();
        mcur = mnext;
        if (c + 2 < CONSN) {
            const unsigned int* gn = g_ent + (c + 2) * ESTRIDE;
            s0 = gn[tid];
            if (tid < ESTRIDE - 128) s1 = gn[128 + tid];
            mnext = g_meta[c + 2];
        }
    }

    // ---- write back (coalesced) ----
    for (int i = 0; i < RPW; i++) {
        int r = rowblk + i;
        if (r < BATCHN) {
            const float* srcr = wbase + i * STRIDE;
            float* dst = out + (size_t)r * NUMA;
            #pragma unroll
            for (int k = 0; k < 16; k++) {
                int idx = lane + 32 * k;
                dst[idx] = srcr[idx];
            }
        }
    }
}

extern "C" void kernel_launch(void* const* d_in, const int* in_sizes, int n_in,
                              void* d_out, int out_size) {
    const float* preds            = (const float*)d_in[0];
    const float* pos_body         = (const float*)d_in[1];
    const float* neg_body         = (const float*)d_in[2];
    const int* head_atom          = (const int*)d_in[3];
    const unsigned char* head_sign = (const unsigned char*)d_in[4];
    float* out = (float*)d_out;

    cudaFuncSetAttribute(solve_kernel, cudaFuncAttributeMaxDynamicSharedMemorySize, SMEM_BYTES);
    prep_kernel<<<CONSN, 128>>>(pos_body, neg_body, head_atom, head_sign);
    solve_kernel<<<GRIDN, 128, SMEM_BYTES>>>(preds, out);
}

// round 6
// speedup vs baseline: 1.3076x; 1.3076x over previous
#include <cuda_runtime.h>
#include <cstdint>

#define BATCHN 16384
#define NUMA   512
#define CONSN  512

#define GROUPS  4                  // row groups per block (4 warps each)
#define RPG     27                 // rows per group; lanes 27..31 duplicate slots 0..4
#define STRIDE  515                // floats per row; word[512]=1.0f (min neutral), [513]=0.0f (max neutral)
#define GROUPF  (RPG*STRIDE)
#define ROWSPB  (GROUPS*RPG)       // 108 rows per block; 152*108 = 16416 >= 16384
#define ECAP    96                 // max entries per list; Binom(512,1/12) mean 42.7, sd 6.3
#define ESTRIDE 192                // pos at [0..96), neg at [96..192)
#define GRIDN   152
#define NTH     512                // 16 warps -> 4 warps per SMSP
#define SMEMW   (GROUPS*GROUPF + 2*ESTRIDE + 2*NTH)   // 57,028 words = 228,112 B (< 232,448 limit)

__device__ unsigned int g_ent[CONSN * ESTRIDE];   // byte offsets (atom*4), padded with neutral offsets
__device__ int4         g_meta[CONSN];            // {np4 chunks, nn4 chunks, head byte-offset, sign}

// ---------------------------------------------------------------------------
// Prep: compact dense masks into sparse per-constraint offset lists.
// Empty lists (prob ~1e-18) fall out naturally: chunk count 0 -> neutral result.
// head_sign decoded defensively (uint8 vs 4-byte int/float widening of bool).
// ---------------------------------------------------------------------------
__global__ void prep_kernel(const float* __restrict__ pos_body,
                            const float* __restrict__ neg_body,
                            const int* __restrict__ head_atom,
                            const unsigned char* __restrict__ head_sign) {
    int c = blockIdx.x;
    __shared__ int cnt[2];
    __shared__ int is_u8;
    if (threadIdx.x == 0) { cnt[0] = 0; cnt[1] = 0; is_u8 = 0; }
    __syncthreads();
    for (int t = threadIdx.x; t < CONSN; t += blockDim.x) {
        if ((t & 3) && head_sign[t]) atomicOr(&is_u8, 1);
    }
    const float* pr = pos_body + c * NUMA;
    const float* nr = neg_body + c * NUMA;
    for (int j = threadIdx.x; j < NUMA; j += blockDim.x) {
        if (pr[j] > 0.5f) {
            int k = atomicAdd(&cnt[0], 1);
            if (k < ECAP) g_ent[c * ESTRIDE + k] = (unsigned)(j * 4);
        }
        if (nr[j] > 0.5f) {
            int k = atomicAdd(&cnt[1], 1);
            if (k < ECAP) g_ent[c * ESTRIDE + ECAP + k] = (unsigned)(j * 4);
        }
    }
    __syncthreads();
    if (threadIdx.x == 0) {
        int np = min(cnt[0], ECAP), nn = min(cnt[1], ECAP);
        int np4 = (np + 3) >> 2;
        int nn4 = (nn + 3) >> 2;
        for (int k = np; k < np4 * 4; k++) g_ent[c * ESTRIDE + k]        = 512u * 4u; // 1.0f (min neutral)
        for (int k = nn; k < nn4 * 4; k++) g_ent[c * ESTRIDE + ECAP + k] = 513u * 4u; // 0.0f (max neutral)
        int sign = is_u8 ? (head_sign[c] != 0)
                         : (((const unsigned int*)head_sign)[c] != 0u);
        g_meta[c] = make_int4(np4, nn4, head_atom[c] * 4, sign);
    }
}

// ---------------------------------------------------------------------------
// Solver: 16 warps. Warp group g (4 warps) owns 27 rows. Within a group,
// role 0/1 compute the two halves of the pos list (running min of p), role
// 2/3 the halves of the neg list (running max of p). Partials combine via a
// double-buffered SMEM buffer with ONE barrier per constraint; the head
// update is applied redundantly by all 4 warps (idempotent identical writes),
// so no second barrier is needed.
// Gathers are conflict-free: all lanes read the same (broadcast) atom at
// odd-stride row slots; duplicate lanes (27..31) broadcast with slots 0..4.
// ---------------------------------------------------------------------------
__global__ void __launch_bounds__(NTH, 1)
solve_kernel(const float* __restrict__ preds, float* __restrict__ out) {
    extern __shared__ float smem[];
    float*        rows = smem;
    unsigned int* sbuf = (unsigned int*)(smem + GROUPS * GROUPF);   // 2 x ESTRIDE staged entries
    float*        comb = (float*)(sbuf + 2 * ESTRIDE);              // 2 x NTH partials

    const int tid  = threadIdx.x;
    const int warp = tid >> 5;
    const int lane = tid & 31;
    const int g    = warp >> 2;
    const int role = warp & 3;
    const int slot = (lane >= RPG) ? (lane - RPG) : lane;

    char* lb = (char*)(rows + g * GROUPF + slot * STRIDE);
    const int base_row = blockIdx.x * ROWSPB;

    // ---- load rows: iteration j loads entire row j, fully coalesced ----
    for (int i = tid; i < ROWSPB * NUMA; i += NTH) {
        int r = i >> 9, col = i & (NUMA - 1);
        int gr = base_row + r; if (gr >= BATCHN) gr = BATCHN - 1;
        rows[(r / RPG) * GROUPF + (r % RPG) * STRIDE + col] = preds[(size_t)gr * NUMA + col];
    }
    if (tid < ROWSPB) {
        float* rp = rows + (tid / RPG) * GROUPF + (tid % RPG) * STRIDE;
        rp[512] = 1.0f; rp[513] = 0.0f;
    }

    // ---- stage constraint 0; register-prefetch constraint 1 ----
    if (tid < ESTRIDE) sbuf[tid] = g_ent[tid];
    int4 mcur = g_meta[0];
    unsigned int sreg = 0;
    if (tid < ESTRIDE) sreg = g_ent[ESTRIDE + tid];
    int4 mnext = g_meta[1];
    __syncthreads();

    for (int c = 0; c < CONSN; c++) {
        const uint4* pl = (const uint4*)(sbuf + (c & 1) * ESTRIDE);
        const bool isPos = (role < 2);
        const uint4* basep = isPos ? pl : (pl + ECAP / 4);
        const int n4 = isPos ? mcur.x : mcur.y;
        const int h  = (n4 + 1) >> 1;
        const int k0 = (role & 1) ? h : 0;
        const int k1 = (role & 1) ? n4 : h;

        float v;
        if (isPos) {
            float a0 = 1.0f, a1 = 1.0f, a2 = 1.0f, a3 = 1.0f;
            #pragma unroll 2
            for (int k = k0; k < k1; k++) {
                uint4 e = basep[k];
                a0 = fminf(a0, *(const float*)(lb + e.x));
                a1 = fminf(a1, *(const float*)(lb + e.y));
                a2 = fminf(a2, *(const float*)(lb + e.z));
                a3 = fminf(a3, *(const float*)(lb + e.w));
            }
            v = fminf(fminf(a0, a1), fminf(a2, a3));
        } else {
            float b0 = 0.0f, b1 = 0.0f, b2 = 0.0f, b3 = 0.0f;
            #pragma unroll 2
            for (int k = k0; k < k1; k++) {
                uint4 e = basep[k];
                b0 = fmaxf(b0, *(const float*)(lb + e.x));
                b1 = fmaxf(b1, *(const float*)(lb + e.y));
                b2 = fmaxf(b2, *(const float*)(lb + e.z));
                b3 = fmaxf(b3, *(const float*)(lb + e.w));
            }
            v = fmaxf(fmaxf(b0, b1), fmaxf(b2, b3));
        }

        float* combw = comb + (c & 1) * NTH;
        combw[warp * 32 + lane] = v;

        // commit staged entries for c+1 (loaded last iteration)
        if (c + 1 < CONSN && tid < ESTRIDE)
            sbuf[((c + 1) & 1) * ESTRIDE + tid] = sreg;

        __syncthreads();

        // combine partials; every warp of the group applies the (idempotent) head update
        {
            const float* cb = combw + (g << 7);   // g*4 warps * 32 lanes
            float c0 = cb[slot], c1 = cb[32 + slot], c2 = cb[64 + slot], c3 = cb[96 + slot];
            float mnp = fminf(c0, c1);
            float mxn = fmaxf(c2, c3);
            float cand = 1.0f - fmaxf(1.0f - mnp, mxn);   // >= 0: neutrals fold the zeros column
            float prev = *(const float*)(lb + mcur.z);
            float upd  = mcur.w ? fmaxf(prev, cand) : fminf(prev, 1.0f - cand);
            *(float*)(lb + mcur.z) = upd;
        }

        mcur = mnext;
        if (c + 2 < CONSN) {
            if (tid < ESTRIDE) sreg = g_ent[(c + 2) * ESTRIDE + tid];
            mnext = g_meta[c + 2];
        }
    }

    __syncthreads();

    // ---- write back (coalesced) ----
    for (int i = tid; i < ROWSPB * NUMA; i += NTH) {
        int r = i >> 9, col = i & (NUMA - 1);
        int gr = base_row + r;
        if (gr < BATCHN)
            out[(size_t)gr * NUMA + col] = rows[(r / RPG) * GROUPF + (r % RPG) * STRIDE + col];
    }
}

extern "C" void kernel_launch(void* const* d_in, const int* in_sizes, int n_in,
                              void* d_out, int out_size) {
    const float* preds             = (const float*)d_in[0];
    const float* pos_body          = (const float*)d_in[1];
    const float* neg_body          = (const float*)d_in[2];
    const int* head_atom           = (const int*)d_in[3];
    const unsigned char* head_sign = (const unsigned char*)d_in[4];
    float* out = (float*)d_out;

    cudaFuncSetAttribute(solve_kernel, cudaFuncAttributeMaxDynamicSharedMemorySize, SMEMW * 4);
    prep_kernel<<<CONSN, 128>>>(pos_body, neg_body, head_atom, head_sign);
    solve_kernel<<<GRIDN, NTH, SMEMW * 4>>>(preds, out);
}